// round 1
// baseline (speedup 1.0000x reference)
#include <cuda_runtime.h>
#include <math.h>

#define NMAX 100000
#define EMAX 1600000
#define HCD 128
#define NGRP 64
#define NCLS 10

// ---------------- static device scratch (no runtime allocation) ----------------
__device__ float  g_h[(size_t)NMAX * HCD];     // GEMM output (pre-aggregation features)
__device__ float  g_act[(size_t)NMAX * HCD];   // aggregated/activated features
__device__ int    g_srcs[EMAX];                // src index, sorted by dst (CSR)
__device__ float4 g_le[3][EMAX];               // per-edge attention-edge term, per layer, CSR order
__device__ float4 g_ex[EMAX];                  // per-edge exp(logit - max)
__device__ int    g_cnt[NMAX];                 // dst degree histogram
__device__ int    g_rowptr[NMAX + 1];
__device__ int    g_woff[NMAX];
__device__ int    g_bsum[1024];
__device__ int    g_boff[1024];
__device__ float4 g_ls[NMAX];                  // per-node alpha_src (4 heads)
__device__ float4 g_ld[NMAX];                  // per-node alpha_dst (4 heads)
__device__ float  g_ve[3 * 16 * 4];            // We·aE  [layer][f][h]
__device__ float  g_leself[12];                // mean(ea)·ve per layer per head
__device__ float  g_easum[16];
__device__ float  g_gemb[NGRP * HCD];
__device__ float  g_gcnt[NGRP];

// ---------------- helpers ----------------
__device__ __forceinline__ float lrelu(float x) { return x > 0.f ? x : 0.2f * x; }

__device__ __forceinline__ unsigned long long pk2(float x, float y) {
    unsigned long long r;
    asm("mov.b64 %0, {%1,%2};" : "=l"(r) : "r"(__float_as_uint(x)), "r"(__float_as_uint(y)));
    return r;
}
__device__ __forceinline__ void fma2(unsigned long long& d, unsigned long long a, unsigned long long b) {
    asm("fma.rn.f32x2 %0, %1, %2, %0;" : "+l"(d) : "l"(a), "l"(b));
}
__device__ __forceinline__ float lo2(unsigned long long v) { return __uint_as_float((unsigned)(v & 0xffffffffull)); }
__device__ __forceinline__ float hi2(unsigned long long v) { return __uint_as_float((unsigned)(v >> 32)); }

// ---------------- init / preprocessing ----------------
__global__ void k_zero(int n) {
    int i = blockIdx.x * blockDim.x + threadIdx.x;
    if (i < n) g_cnt[i] = 0;
    if (i < 16) g_easum[i] = 0.f;
    if (i < NGRP * HCD) g_gemb[i] = 0.f;
    if (i < NGRP) g_gcnt[i] = 0.f;
}

__global__ void k_hist(const int* __restrict__ dst, int E) {
    int e = blockIdx.x * blockDim.x + threadIdx.x;
    if (e < E) atomicAdd(&g_cnt[dst[e]], 1);
}

__global__ void k_scanA(int n) {
    __shared__ int sh[256];
    int base = blockIdx.x * 1024;
    int s = 0;
    for (int i = threadIdx.x; i < 1024; i += 256) {
        int idx = base + i;
        if (idx < n) s += g_cnt[idx];
    }
    sh[threadIdx.x] = s; __syncthreads();
    for (int d = 128; d > 0; d >>= 1) {
        if (threadIdx.x < d) sh[threadIdx.x] += sh[threadIdx.x + d];
        __syncthreads();
    }
    if (threadIdx.x == 0) g_bsum[blockIdx.x] = sh[0];
}

__global__ void k_scanB(int nchunks, int n) {
    if (threadIdx.x == 0) {
        int run = 0;
        for (int b = 0; b < nchunks; b++) { g_boff[b] = run; run += g_bsum[b]; }
        g_rowptr[n] = run;
    }
}

__global__ void k_scanC(int n) {
    __shared__ int sh[256];
    int base = blockIdx.x * 1024 + threadIdx.x * 4;
    int v[4];
#pragma unroll
    for (int j = 0; j < 4; j++) { int idx = base + j; v[j] = (idx < n) ? g_cnt[idx] : 0; }
    int s = v[0] + v[1] + v[2] + v[3];
    sh[threadIdx.x] = s; __syncthreads();
    for (int d = 1; d < 256; d <<= 1) {
        int add = (threadIdx.x >= (unsigned)d) ? sh[threadIdx.x - d] : 0;
        __syncthreads();
        sh[threadIdx.x] += add;
        __syncthreads();
    }
    int off = g_boff[blockIdx.x] + sh[threadIdx.x] - s;
#pragma unroll
    for (int j = 0; j < 4; j++) {
        int idx = base + j;
        if (idx < n) { g_rowptr[idx] = off; g_woff[idx] = off; off += v[j]; }
    }
}

__global__ void k_easum(const float4* __restrict__ ea4, int E) {
    float s[16];
#pragma unroll
    for (int f = 0; f < 16; f++) s[f] = 0.f;
    for (int e = blockIdx.x * blockDim.x + threadIdx.x; e < E; e += gridDim.x * blockDim.x) {
#pragma unroll
        for (int q = 0; q < 4; q++) {
            float4 v = ea4[(size_t)e * 4 + q];
            s[q * 4 + 0] += v.x; s[q * 4 + 1] += v.y; s[q * 4 + 2] += v.z; s[q * 4 + 3] += v.w;
        }
    }
    __shared__ float sm[16];
    if (threadIdx.x < 16) sm[threadIdx.x] = 0.f;
    __syncthreads();
#pragma unroll
    for (int f = 0; f < 16; f++) atomicAdd(&sm[f], s[f]);
    __syncthreads();
    if (threadIdx.x < 16) atomicAdd(&g_easum[threadIdx.x], sm[threadIdx.x]);
}

__global__ void k_ve(const float* We1, const float* aE1,
                     const float* We2, const float* aE2,
                     const float* We3, const float* aE3, int E) {
    int idx = threadIdx.x;
    const float* Wes[3] = { We1, We2, We3 };
    const float* aEs[3] = { aE1, aE2, aE3 };
    if (idx < 192) {
        int l = idx >> 6, f = (idx >> 2) & 15, h = idx & 3;
        const float* We = Wes[l]; const float* aE = aEs[l];
        float s = 0.f;
        for (int c = 0; c < 32; c++) s += We[f * 128 + h * 32 + c] * aE[h * 32 + c];
        g_ve[l * 64 + f * 4 + h] = s;
    }
    __syncthreads();
    if (idx < 12) {
        int l = idx >> 2, h = idx & 3;
        float inv = 1.f / (float)E;
        float s = 0.f;
        for (int f = 0; f < 16; f++) s += g_easum[f] * inv * g_ve[l * 64 + f * 4 + h];
        g_leself[l * 4 + h] = s;
    }
}

__global__ void k_scatter(const int* __restrict__ src, const int* __restrict__ dst,
                          const float4* __restrict__ ea4, int E) {
    int e = blockIdx.x * blockDim.x + threadIdx.x;
    if (e >= E) return;
    int d = dst[e];
    int pos = atomicAdd(&g_woff[d], 1);
    g_srcs[pos] = src[e];
    float a[16];
#pragma unroll
    for (int q = 0; q < 4; q++) {
        float4 v = ea4[(size_t)e * 4 + q];
        a[q * 4 + 0] = v.x; a[q * 4 + 1] = v.y; a[q * 4 + 2] = v.z; a[q * 4 + 3] = v.w;
    }
#pragma unroll
    for (int l = 0; l < 3; l++) {
        const float4* vel = (const float4*)&g_ve[l * 64];
        float r0 = 0.f, r1 = 0.f, r2 = 0.f, r3 = 0.f;
#pragma unroll
        for (int f = 0; f < 16; f++) {
            float4 vv = __ldg(&vel[f]);
            float av = a[f];
            r0 += av * vv.x; r1 += av * vv.y; r2 += av * vv.z; r3 += av * vv.w;
        }
        g_le[l][pos] = make_float4(r0, r1, r2, r3);
    }
}

// ---------------- GEMM: C[n,128] = A[n,K] @ W[K,128]  (packed f32x2 FMA) ----------------
__global__ void __launch_bounds__(256) k_gemm(const float* __restrict__ A,
                                              const float* __restrict__ W,
                                              float* __restrict__ C, int n, int K) {
    __shared__ float As[32 * 66];   // [k][row], stride 66 keeps 8B alignment + low conflicts
    __shared__ float Bs[32 * 128];  // [k][col]
    int tid = threadIdx.x;
    int row0 = blockIdx.x * 64;
    int tx = tid & 31, ty = tid >> 5;
    int c0 = tx * 4;
    int r0 = ty * 8;

    unsigned long long acc[4][4];
#pragma unroll
    for (int p = 0; p < 4; p++)
#pragma unroll
        for (int j = 0; j < 4; j++) acc[p][j] = 0ull;

    for (int k0 = 0; k0 < K; k0 += 32) {
        int kk = tid & 31, rb = tid >> 5;
#pragma unroll
        for (int j = 0; j < 8; j++) {
            int r = rb + j * 8;
            int gr = row0 + r;
            float v = (gr < n) ? A[(size_t)gr * K + k0 + kk] : 0.f;
            As[kk * 66 + r] = v;
        }
        int nn = tid & 127;
#pragma unroll
        for (int j = 0; j < 16; j++) {
            int k2 = (tid >> 7) + j * 2;
            Bs[k2 * 128 + nn] = W[(size_t)(k0 + k2) * 128 + nn];
        }
        __syncthreads();
#pragma unroll
        for (int k = 0; k < 32; k++) {
            float4 bv = *(const float4*)&Bs[k * 128 + c0];
            unsigned long long bb0 = pk2(bv.x, bv.x);
            unsigned long long bb1 = pk2(bv.y, bv.y);
            unsigned long long bb2 = pk2(bv.z, bv.z);
            unsigned long long bb3 = pk2(bv.w, bv.w);
            const unsigned long long* a2 = (const unsigned long long*)&As[k * 66 + r0];
#pragma unroll
            for (int p = 0; p < 4; p++) {
                unsigned long long av = a2[p];
                fma2(acc[p][0], av, bb0);
                fma2(acc[p][1], av, bb1);
                fma2(acc[p][2], av, bb2);
                fma2(acc[p][3], av, bb3);
            }
        }
        __syncthreads();
    }
#pragma unroll
    for (int p = 0; p < 4; p++) {
        int r = row0 + r0 + 2 * p;
        if (r < n) {
            float4 v = make_float4(lo2(acc[p][0]), lo2(acc[p][1]), lo2(acc[p][2]), lo2(acc[p][3]));
            *(float4*)&C[(size_t)r * 128 + c0] = v;
        }
        if (r + 1 < n) {
            float4 v = make_float4(hi2(acc[p][0]), hi2(acc[p][1]), hi2(acc[p][2]), hi2(acc[p][3]));
            *(float4*)&C[(size_t)(r + 1) * 128 + c0] = v;
        }
    }
}

// ---------------- per-node attention scalars ----------------
__global__ void k_lsld(const float* __restrict__ h, const float* __restrict__ aS,
                       const float* __restrict__ aD, int n) {
    int w = (blockIdx.x * blockDim.x + threadIdx.x) >> 5;
    int lane = threadIdx.x & 31;
    if (w >= n) return;
    float s[4], d[4];
#pragma unroll
    for (int hh = 0; hh < 4; hh++) {
        float v = h[(size_t)w * 128 + hh * 32 + lane];
        s[hh] = v * aS[hh * 32 + lane];
        d[hh] = v * aD[hh * 32 + lane];
    }
#pragma unroll
    for (int off = 16; off > 0; off >>= 1) {
#pragma unroll
        for (int hh = 0; hh < 4; hh++) {
            s[hh] += __shfl_xor_sync(0xffffffffu, s[hh], off);
            d[hh] += __shfl_xor_sync(0xffffffffu, d[hh], off);
        }
    }
    if (lane == 0) {
        g_ls[w] = make_float4(s[0], s[1], s[2], s[3]);
        g_ld[w] = make_float4(d[0], d[1], d[2], d[3]);
    }
}

// ---------------- edge aggregation: segment softmax + weighted gather ----------------
template <bool ELU>
__global__ void __launch_bounds__(256) k_agg(const float* __restrict__ h,
                                             const float* __restrict__ bias,
                                             float* __restrict__ out, int n, int layer) {
    int w = (blockIdx.x * blockDim.x + threadIdx.x) >> 5;
    int lane = threadIdx.x & 31;
    if (w >= n) return;
    int beg = g_rowptr[w], end = g_rowptr[w + 1];
    float4 ldv = g_ld[w];
    float4 lsv = g_ls[w];
    float4 lself = *(const float4*)&g_leself[layer * 4];
    const float4* le = g_le[layer];

    float sl[4];
    sl[0] = lrelu(lsv.x + ldv.x + lself.x);
    sl[1] = lrelu(lsv.y + ldv.y + lself.y);
    sl[2] = lrelu(lsv.z + ldv.z + lself.z);
    sl[3] = lrelu(lsv.w + ldv.w + lself.w);
    float mx[4] = { sl[0], sl[1], sl[2], sl[3] };

    for (int i = beg + lane; i < end; i += 32) {
        int s = g_srcs[i];
        float4 l4 = g_ls[s];
        float4 e4 = le[i];
        mx[0] = fmaxf(mx[0], lrelu(l4.x + ldv.x + e4.x));
        mx[1] = fmaxf(mx[1], lrelu(l4.y + ldv.y + e4.y));
        mx[2] = fmaxf(mx[2], lrelu(l4.z + ldv.z + e4.z));
        mx[3] = fmaxf(mx[3], lrelu(l4.w + ldv.w + e4.w));
    }
#pragma unroll
    for (int off = 16; off > 0; off >>= 1)
#pragma unroll
        for (int hh = 0; hh < 4; hh++)
            mx[hh] = fmaxf(mx[hh], __shfl_xor_sync(0xffffffffu, mx[hh], off));

    float den[4] = { 0.f, 0.f, 0.f, 0.f };
    for (int i = beg + lane; i < end; i += 32) {
        int s = g_srcs[i];
        float4 l4 = g_ls[s];
        float4 e4 = le[i];
        float4 ex;
        ex.x = __expf(lrelu(l4.x + ldv.x + e4.x) - mx[0]);
        ex.y = __expf(lrelu(l4.y + ldv.y + e4.y) - mx[1]);
        ex.z = __expf(lrelu(l4.z + ldv.z + e4.z) - mx[2]);
        ex.w = __expf(lrelu(l4.w + ldv.w + e4.w) - mx[3]);
        g_ex[i] = ex;
        den[0] += ex.x; den[1] += ex.y; den[2] += ex.z; den[3] += ex.w;
    }
#pragma unroll
    for (int off = 16; off > 0; off >>= 1)
#pragma unroll
        for (int hh = 0; hh < 4; hh++)
            den[hh] += __shfl_xor_sync(0xffffffffu, den[hh], off);

    float exs[4];
#pragma unroll
    for (int hh = 0; hh < 4; hh++) {
        exs[hh] = __expf(sl[hh] - mx[hh]);
        den[hh] += exs[hh] + 1e-16f;
    }
    __syncwarp();

    float acc[4];
#pragma unroll
    for (int hh = 0; hh < 4; hh++)
        acc[hh] = exs[hh] * h[(size_t)w * 128 + hh * 32 + lane];

    for (int j = beg; j < end; j++) {
        int s = g_srcs[j];                // warp-broadcast load
        float4 e = g_ex[j];               // warp-broadcast load
        const float* hp = h + (size_t)s * 128 + lane;
        acc[0] += e.x * hp[0];
        acc[1] += e.y * hp[32];
        acc[2] += e.z * hp[64];
        acc[3] += e.w * hp[96];
    }
#pragma unroll
    for (int hh = 0; hh < 4; hh++) {
        float v = acc[hh] / den[hh] + bias[hh * 32 + lane];
        if (ELU) v = v > 0.f ? v : (__expf(v) - 1.f);
        out[(size_t)w * 128 + hh * 32 + lane] = v;
    }
}

// ---------------- heads ----------------
__global__ void __launch_bounds__(128) k_loc(const float* __restrict__ h,
                                             const float* __restrict__ Wl1, const float* __restrict__ bl1,
                                             const float* __restrict__ Wl2, const float* __restrict__ bl2,
                                             float* __restrict__ out, int n) {
    __shared__ float W1s[128 * 64];
    __shared__ float W2s[64];
    __shared__ float b1s[64];
    for (int i = threadIdx.x; i < 128 * 64; i += 128) W1s[i] = Wl1[i];
    if (threadIdx.x < 64) { W2s[threadIdx.x] = Wl2[threadIdx.x]; b1s[threadIdx.x] = bl1[threadIdx.x]; }
    __syncthreads();
    int nd = blockIdx.x * 128 + threadIdx.x;
    if (nd >= n) return;
    float t[64];
#pragma unroll
    for (int j = 0; j < 64; j++) t[j] = b1s[j];
    const float* hr = h + (size_t)nd * 128;
    for (int c = 0; c < 128; c++) {
        float hv = hr[c];
#pragma unroll
        for (int j = 0; j < 64; j++) t[j] += hv * W1s[c * 64 + j];
    }
    float o = bl2[0];
#pragma unroll
    for (int j = 0; j < 64; j++) o += fmaxf(t[j], 0.f) * W2s[j];
    out[640 + nd] = o;
}

__global__ void k_pool(const float* __restrict__ h, const int* __restrict__ batch, int n) {
    int base = blockIdx.x * 1024;
    int tid = threadIdx.x;  // 128 threads = 128 channels
    int endr = min(base + 1024, n);
    float acc = 0.f; int cur = -1; int cnt = 0;
    for (int r = base; r < endr; r++) {
        int g = batch[r];
        if (g != cur) {
            if (cur >= 0) {
                atomicAdd(&g_gemb[cur * 128 + tid], acc);
                if (tid == 0) atomicAdd(&g_gcnt[cur], (float)cnt);
            }
            acc = 0.f; cnt = 0; cur = g;
        }
        acc += h[(size_t)r * 128 + tid];
        cnt++;
    }
    if (cur >= 0) {
        atomicAdd(&g_gemb[cur * 128 + tid], acc);
        if (tid == 0) atomicAdd(&g_gcnt[cur], (float)cnt);
    }
}

__global__ void __launch_bounds__(128) k_class(const float* __restrict__ Wc1, const float* __restrict__ bc1,
                                               const float* __restrict__ Wc2, const float* __restrict__ bc2,
                                               float* __restrict__ out) {
    __shared__ float e[128];
    __shared__ float t[128];
    int g = blockIdx.x, tid = threadIdx.x;
    float cnt = fmaxf(g_gcnt[g], 1.f);
    e[tid] = g_gemb[g * 128 + tid] / cnt;
    __syncthreads();
    float s = bc1[tid];
    for (int c = 0; c < 128; c++) s += e[c] * Wc1[c * 128 + tid];
    t[tid] = fmaxf(s, 0.f);
    __syncthreads();
    if (tid < NCLS) {
        float o = bc2[tid];
        for (int c = 0; c < 128; c++) o += t[c] * Wc2[c * NCLS + tid];
        out[g * NCLS + tid] = o;
    }
}

// ---------------- launch ----------------
extern "C" void kernel_launch(void* const* d_in, const int* in_sizes, int n_in,
                              void* d_out, int out_size) {
    const float* x       = (const float*)d_in[0];
    const int*   ei      = (const int*)d_in[1];
    const float* ea      = (const float*)d_in[2];
    const int*   batch   = (const int*)d_in[3];
    const float* W[3], *aS[3], *aD[3], *We[3], *aE[3], *b[3];
    int p = 4;
    for (int l = 0; l < 3; l++) {
        W[l]  = (const float*)d_in[p++];
        aS[l] = (const float*)d_in[p++];
        aD[l] = (const float*)d_in[p++];
        We[l] = (const float*)d_in[p++];
        aE[l] = (const float*)d_in[p++];
        b[l]  = (const float*)d_in[p++];
    }
    const float* Wc1 = (const float*)d_in[22];
    const float* bc1 = (const float*)d_in[23];
    const float* Wc2 = (const float*)d_in[24];
    const float* bc2 = (const float*)d_in[25];
    const float* Wl1 = (const float*)d_in[26];
    const float* bl1 = (const float*)d_in[27];
    const float* Wl2 = (const float*)d_in[28];
    const float* bl2 = (const float*)d_in[29];

    int n = in_sizes[0] / 64;
    int E = in_sizes[1] / 2;
    const int* src = ei;
    const int* dst = ei + E;
    float* out = (float*)d_out;

    void *p_h = nullptr, *p_act = nullptr;
    cudaGetSymbolAddress(&p_h, g_h);
    cudaGetSymbolAddress(&p_act, g_act);
    float* hbuf = (float*)p_h;
    float* actbuf = (float*)p_act;

    int nch = (n + 1023) / 1024;

    k_zero<<<(n + 255) / 256, 256>>>(n);
    k_hist<<<(E + 255) / 256, 256>>>(dst, E);
    k_scanA<<<nch, 256>>>(n);
    k_scanB<<<1, 32>>>(nch, n);
    k_scanC<<<nch, 256>>>(n);
    k_easum<<<256, 256>>>((const float4*)ea, E);
    k_ve<<<1, 256>>>(We[0], aE[0], We[1], aE[1], We[2], aE[2], E);
    k_scatter<<<(E + 255) / 256, 256>>>(src, dst, (const float4*)ea, E);

    int aggBlocks = (n * 32 + 255) / 256;
    const float* gin = x;
    int K = 64;
    for (int l = 0; l < 3; l++) {
        k_gemm<<<(n + 63) / 64, 256>>>(gin, W[l], hbuf, n, K);
        k_lsld<<<aggBlocks, 256>>>(hbuf, aS[l], aD[l], n);
        if (l < 2)
            k_agg<true><<<aggBlocks, 256>>>(hbuf, b[l], actbuf, n, l);
        else
            k_agg<false><<<aggBlocks, 256>>>(hbuf, b[l], actbuf, n, l);
        gin = actbuf;
        K = 128;
    }

    k_loc<<<(n + 127) / 128, 128>>>(actbuf, Wl1, bl1, Wl2, bl2, out, n);
    k_pool<<<nch, 128>>>(actbuf, batch, n);
    k_class<<<NGRP, 128>>>(Wc1, bc1, Wc2, bc2, out);
}